// round 6
// baseline (speedup 1.0000x reference)
#include <cuda_runtime.h>
#include <cstdint>

#define SCALE_LOGIT 7.2134752044448169f   // TEMP(5) * log2(e)

// ----------------- device scratch (no allocation allowed) -----------------
__device__ __align__(16) float d_Wtp[512 * 128];     // [k=ic*4+p*2+q][oc]; oc<64: theta(scaled), oc>=64: phi
__device__ __align__(16) float d_btp[128];           // theta bias (scaled) | phi bias
__device__ __align__(16) float d_Wg[512 * 64];       // [k][oc]
__device__ __align__(16) float d_bg[64];
__device__ __align__(16) float d_W2[64 * 512];       // [c2][oc*4+p*2+q]
__device__ __align__(16) float d_theta_hi[4 * 64 * 9216]; // [b][c][n] scaled logits, tf32 hi
__device__ __align__(16) float d_theta_lo[4 * 64 * 9216]; // [b][c][n] tf32 lo
__device__ __align__(16) float d_phi_hi[4 * 2304 * 64];   // [b][m][c] tf32 hi (key-major)
__device__ __align__(16) float d_phi_lo[4 * 2304 * 64];   // [b][m][c] tf32 lo
__device__ __align__(16) float d_g[4 * 2304 * 64];        // [b][m][c] tf32-rounded
__device__ __align__(16) float d_omap[4 * 64 * 9216];     // [b][c][n]

__device__ __forceinline__ float ex2f(float x) {
    float r; asm("ex2.approx.f32 %0, %1;" : "=f"(r) : "f"(x)); return r;
}
__device__ __forceinline__ float tf32r(float x) {
    uint32_t u; asm("cvt.rna.tf32.f32 %0, %1;" : "=r"(u) : "f"(x)); return __uint_as_float(u);
}
__device__ __forceinline__ void mma_tf32(float* c, const uint32_t* a, uint32_t b0, uint32_t b1) {
    asm volatile("mma.sync.aligned.m16n8k8.row.col.f32.tf32.tf32.f32 "
                 "{%0,%1,%2,%3},{%4,%5,%6,%7},{%8,%9},{%0,%1,%2,%3};"
                 : "+f"(c[0]), "+f"(c[1]), "+f"(c[2]), "+f"(c[3])
                 : "r"(a[0]), "r"(a[1]), "r"(a[2]), "r"(a[3]), "r"(b0), "r"(b1));
}
__device__ __forceinline__ void ldsm4(uint32_t* r, uint32_t addr) {
    asm volatile("ldmatrix.sync.aligned.m8n8.x4.shared.b16 {%0,%1,%2,%3}, [%4];"
                 : "=r"(r[0]), "=r"(r[1]), "=r"(r[2]), "=r"(r[3]) : "r"(addr));
}

// ----------------- K1a: fuse theta/phi with down0 -----------------
__global__ void fuse_tp(const float* __restrict__ theta_w, const float* __restrict__ phi_w,
                        const float* __restrict__ down_w, const float* __restrict__ down_b) {
    int idx = blockIdx.x * 256 + threadIdx.x;   // 16384
    int oc = idx & 127, ic = idx >> 7;
    const float* wrow = (oc < 64) ? (theta_w + oc * 128) : (phi_w + (oc - 64) * 128);
    float a0 = 0.f, a1 = 0.f, a2 = 0.f, a3 = 0.f, ab = 0.f;
    for (int c = 0; c < 128; c++) {
        float wv = wrow[c];
        float4 dv = *(const float4*)(down_w + (size_t)(c * 128 + ic) * 4);
        a0 += wv * dv.x; a1 += wv * dv.y; a2 += wv * dv.z; a3 += wv * dv.w;
        if (ic == 0) ab += wv * down_b[c];
    }
    float s = (oc < 64) ? SCALE_LOGIT : 1.f;
    d_Wtp[(ic * 4 + 0) * 128 + oc] = a0 * s;
    d_Wtp[(ic * 4 + 1) * 128 + oc] = a1 * s;
    d_Wtp[(ic * 4 + 2) * 128 + oc] = a2 * s;
    d_Wtp[(ic * 4 + 3) * 128 + oc] = a3 * s;
    if (ic == 0) d_btp[oc] = ab * s;
}

// ----------------- K1b: fuse g with down1 -----------------
__global__ void fuse_g(const float* __restrict__ g_w,
                       const float* __restrict__ down_w, const float* __restrict__ down_b) {
    int idx = blockIdx.x * 256 + threadIdx.x;   // 8192
    int oc = idx & 63, ic = idx >> 6;
    const float* wrow = g_w + oc * 128;
    float a0 = 0.f, a1 = 0.f, a2 = 0.f, a3 = 0.f, ab = 0.f;
    for (int c = 0; c < 128; c++) {
        float wv = wrow[c];
        float4 dv = *(const float4*)(down_w + (size_t)(c * 128 + ic) * 4);
        a0 += wv * dv.x; a1 += wv * dv.y; a2 += wv * dv.z; a3 += wv * dv.w;
        if (ic == 0) ab += wv * down_b[c];
    }
    d_Wg[(ic * 4 + 0) * 64 + oc] = a0;
    d_Wg[(ic * 4 + 1) * 64 + oc] = a1;
    d_Wg[(ic * 4 + 2) * 64 + oc] = a2;
    d_Wg[(ic * 4 + 3) * 64 + oc] = a3;
    if (ic == 0) d_bg[oc] = ab;
}

// ----------------- K1c: fuse o_w with up_w -----------------
__global__ void fuse_w2(const float* __restrict__ o_w, const float* __restrict__ up_w) {
    int idx = blockIdx.x * 256 + threadIdx.x;   // 8192
    int c2 = idx & 63, oc = idx >> 6;
    float a0 = 0.f, a1 = 0.f, a2 = 0.f, a3 = 0.f;
    for (int och = 0; och < 128; och++) {
        float wv = o_w[och * 64 + c2];
        float4 dv = *(const float4*)(up_w + (size_t)(och * 128 + oc) * 4);
        a0 += wv * dv.x; a1 += wv * dv.y; a2 += wv * dv.z; a3 += wv * dv.w;
    }
    d_W2[c2 * 512 + oc * 4 + 0] = a0;
    d_W2[c2 * 512 + oc * 4 + 1] = a1;
    d_W2[c2 * 512 + oc * 4 + 2] = a2;
    d_W2[c2 * 512 + oc * 4 + 3] = a3;
}

// ----------------- K2: fused theta+phi conv (2x2/s2, K=512) + phi maxpool -----------------
// grid (3, 24, 4), 256 threads; tile = 4 out-rows x 32 out-cols (128 px), 128 oc
// thread tile: 8 px (2 rows x 4 cols) x 8 oc
__global__ __launch_bounds__(256) void conv_tp(const float* __restrict__ X) {
    __shared__ float As[32 * 128];   // [k_local][px = ro*32 + jc]
    __shared__ float Ws[32 * 128];   // [k_local][oc]
    int b = blockIdx.z, tr = blockIdx.y, tc = blockIdx.x;
    int tid = threadIdx.x;
    int ocg = tid & 15, pxg = tid >> 4;
    int rp = pxg >> 3, cq = pxg & 7;
    float acc[8][8];
    #pragma unroll
    for (int i = 0; i < 8; i++)
        #pragma unroll
        for (int u = 0; u < 8; u++) acc[i][u] = 0.f;
    const float* Xb = X + (size_t)b * 128 * 192 * 192;
    for (int icb = 0; icb < 16; icb++) {
        #pragma unroll
        for (int t = 0; t < 4; t++)
            ((float4*)Ws)[t * 256 + tid] = ((const float4*)(d_Wtp + icb * 4096))[t * 256 + tid];
        #pragma unroll
        for (int t = 0; t < 8; t++) {
            int i = t * 256 + tid;
            int jc = i & 31, p = (i >> 5) & 1, ro = (i >> 6) & 3, ic8 = i >> 8;
            float2 v = ((const float2*)(Xb + ((size_t)(icb * 8 + ic8) * 192
                         + 8 * tr + 2 * ro + p) * 192 + tc * 64))[jc];
            As[(ic8 * 4 + p * 2 + 0) * 128 + ro * 32 + jc] = v.x;
            As[(ic8 * 4 + p * 2 + 1) * 128 + ro * 32 + jc] = v.y;
        }
        __syncthreads();
        #pragma unroll 2
        for (int k = 0; k < 32; k++) {
            float4 alo = *(const float4*)(As + k * 128 + (2 * rp) * 32 + 4 * cq);
            float4 ahi = *(const float4*)(As + k * 128 + (2 * rp + 1) * 32 + 4 * cq);
            float4 w0 = *(const float4*)(Ws + k * 128 + ocg * 8);
            float4 w1 = *(const float4*)(Ws + k * 128 + ocg * 8 + 4);
            float av[8] = {alo.x, alo.y, alo.z, alo.w, ahi.x, ahi.y, ahi.z, ahi.w};
            float wv[8] = {w0.x, w0.y, w0.z, w0.w, w1.x, w1.y, w1.z, w1.w};
            #pragma unroll
            for (int px = 0; px < 8; px++)
                #pragma unroll
                for (int u = 0; u < 8; u++)
                    acc[px][u] += av[px] * wv[u];
        }
        __syncthreads();
    }
    if (ocg < 8) {   // theta (scaled): hi/lo split, [b][c][n]
        #pragma unroll
        for (int u = 0; u < 8; u++) {
            int c = ocg * 8 + u;
            float bb = d_btp[c];
            float* dh = d_theta_hi + ((size_t)b * 64 + c) * 9216;
            float* dl = d_theta_lo + ((size_t)b * 64 + c) * 9216;
            #pragma unroll
            for (int r2 = 0; r2 < 2; r2++) {
                int n = (4 * tr + 2 * rp + r2) * 96 + tc * 32 + 4 * cq;
                #pragma unroll
                for (int jj = 0; jj < 4; jj++) {
                    float v = acc[r2 * 4 + jj][u] + bb;
                    float h = tf32r(v);
                    dh[n + jj] = h;
                    dl[n + jj] = tf32r(v - h);
                }
            }
        }
    } else {         // phi, maxpooled 2x2: hi/lo split, key-major [b][m][c]
        #pragma unroll
        for (int u = 0; u < 8; u++) {
            int c = (ocg - 8) * 8 + u;
            float bv = d_btp[64 + c];
            int m0 = (2 * tr + rp) * 48 + tc * 16 + 2 * cq;
            float p0 = fmaxf(fmaxf(acc[0][u], acc[1][u]), fmaxf(acc[4][u], acc[5][u])) + bv;
            float p1 = fmaxf(fmaxf(acc[2][u], acc[3][u]), fmaxf(acc[6][u], acc[7][u])) + bv;
            float h0 = tf32r(p0), h1 = tf32r(p1);
            size_t a0 = ((size_t)b * 2304 + m0) * 64 + c;
            d_phi_hi[a0] = h0;      d_phi_lo[a0] = tf32r(p0 - h0);
            d_phi_hi[a0 + 64] = h1; d_phi_lo[a0 + 64] = tf32r(p1 - h1);
        }
    }
}

// ----------------- K3: fused g conv (2x2/s2, K=512) + maxpool -----------------
// grid (3, 12, 4), 256 threads; tile = 8 out-rows x 32 out-cols (256 px), 64 oc
__global__ __launch_bounds__(256) void conv_g(const float* __restrict__ Y) {
    __shared__ float As[32 * 256];
    __shared__ float Ws[32 * 64];
    int b = blockIdx.z, tr = blockIdx.y, tc = blockIdx.x;
    int tid = threadIdx.x;
    int ocg = tid & 7, pxg = tid >> 3;
    int rp = pxg >> 3, cq = pxg & 7;
    float acc[8][8];
    #pragma unroll
    for (int i = 0; i < 8; i++)
        #pragma unroll
        for (int u = 0; u < 8; u++) acc[i][u] = 0.f;
    const float* Yb = Y + (size_t)b * 128 * 192 * 192;
    for (int icb = 0; icb < 16; icb++) {
        #pragma unroll
        for (int t = 0; t < 2; t++)
            ((float4*)Ws)[t * 256 + tid] = ((const float4*)(d_Wg + icb * 2048))[t * 256 + tid];
        #pragma unroll
        for (int t = 0; t < 16; t++) {
            int i = t * 256 + tid;
            int jc = i & 31, p = (i >> 5) & 1, ro = (i >> 6) & 7, ic8 = i >> 9;
            float2 v = ((const float2*)(Yb + ((size_t)(icb * 8 + ic8) * 192
                         + 16 * tr + 2 * ro + p) * 192 + tc * 64))[jc];
            As[(ic8 * 4 + p * 2 + 0) * 256 + ro * 32 + jc] = v.x;
            As[(ic8 * 4 + p * 2 + 1) * 256 + ro * 32 + jc] = v.y;
        }
        __syncthreads();
        #pragma unroll 2
        for (int k = 0; k < 32; k++) {
            float4 alo = *(const float4*)(As + k * 256 + (2 * rp) * 32 + 4 * cq);
            float4 ahi = *(const float4*)(As + k * 256 + (2 * rp + 1) * 32 + 4 * cq);
            float4 w0 = *(const float4*)(Ws + k * 64 + ocg * 8);
            float4 w1 = *(const float4*)(Ws + k * 64 + ocg * 8 + 4);
            float av[8] = {alo.x, alo.y, alo.z, alo.w, ahi.x, ahi.y, ahi.z, ahi.w};
            float wv[8] = {w0.x, w0.y, w0.z, w0.w, w1.x, w1.y, w1.z, w1.w};
            #pragma unroll
            for (int px = 0; px < 8; px++)
                #pragma unroll
                for (int u = 0; u < 8; u++)
                    acc[px][u] += av[px] * wv[u];
        }
        __syncthreads();
    }
    int m0 = (4 * tr + rp) * 48 + tc * 16 + 2 * cq;   // pooled
    float r0[8], r1[8];
    #pragma unroll
    for (int u = 0; u < 8; u++) {
        float bv = d_bg[ocg * 8 + u];
        r0[u] = tf32r(fmaxf(fmaxf(acc[0][u], acc[1][u]), fmaxf(acc[4][u], acc[5][u])) + bv);
        r1[u] = tf32r(fmaxf(fmaxf(acc[2][u], acc[3][u]), fmaxf(acc[6][u], acc[7][u])) + bv);
    }
    float* g0 = d_g + ((size_t)b * 2304 + m0) * 64 + ocg * 8;
    *(float4*)(g0)      = make_float4(r0[0], r0[1], r0[2], r0[3]);
    *(float4*)(g0 + 4)  = make_float4(r0[4], r0[5], r0[6], r0[7]);
    *(float4*)(g0 + 64) = make_float4(r1[0], r1[1], r1[2], r1[3]);
    *(float4*)(g0 + 68) = make_float4(r1[4], r1[5], r1[6], r1[7]);
}

// ----------------- K4: tf32 tensor-core flash attention (Br=64, Bc=64, C=64) -----------------
// grid (144, 4), 128 threads (4 warps, one m16 q-row tile each)
__global__ __launch_bounds__(128) void attn_tc() {
    extern __shared__ float sm[];
    float* Khi = sm;                    // [64 key][68]
    float* Klo = sm + 4352;             // [64 key][68]
    float* Gs  = sm + 2 * 4352;         // [64 key][72]
    float* Ps  = sm + 2 * 4352 + 4608;  // [64 q][68]  (also reused as O staging [ch][q])
    int b = blockIdx.y;
    int n0 = blockIdx.x * 64;
    int tid = threadIdx.x;
    int w = tid >> 5, lane = tid & 31;
    int g = lane >> 2, tig = lane & 3;
    int qa = n0 + w * 16 + g, qb = qa + 8;

    uint32_t sm_u32 = (uint32_t)__cvta_generic_to_shared(sm);
    uint32_t khi_base = sm_u32;
    uint32_t ps_base  = sm_u32 + (2u * 4352 + 4608) * 4;
    int lr = lane & 7, sel = lane >> 3;
    // K LDSM per-lane offset: mats = {Khi b0, Khi b1, Klo b0, Klo b1}
    uint32_t koff = (uint32_t)(lr * 272 + (sel & 1) * 16 + ((sel >> 1) ? 4352 * 4 : 0));
    // P LDSM per-lane offset: mats = {rows+0 chunk0, rows+8 chunk0, rows+0 chunk1, rows+8 chunk1}
    uint32_t poff = (uint32_t)(((lane & 7) + (sel & 1) * 8) * 272 + (sel >> 1) * 16)
                    + (uint32_t)(w * 16 * 272);

    // Q fragments for all 8 k-steps (hi and lo), held in registers for the whole kernel
    uint32_t Ahi[8][4], Alo[8][4];
    {
        const float* th = d_theta_hi + (size_t)b * 64 * 9216;
        const float* tl = d_theta_lo + (size_t)b * 64 * 9216;
        #pragma unroll
        for (int ks = 0; ks < 8; ks++) {
            int c0 = ks * 8 + tig, c1 = c0 + 4;
            Ahi[ks][0] = __float_as_uint(th[(size_t)c0 * 9216 + qa]);
            Ahi[ks][1] = __float_as_uint(th[(size_t)c0 * 9216 + qb]);
            Ahi[ks][2] = __float_as_uint(th[(size_t)c1 * 9216 + qa]);
            Ahi[ks][3] = __float_as_uint(th[(size_t)c1 * 9216 + qb]);
            Alo[ks][0] = __float_as_uint(tl[(size_t)c0 * 9216 + qa]);
            Alo[ks][1] = __float_as_uint(tl[(size_t)c0 * 9216 + qb]);
            Alo[ks][2] = __float_as_uint(tl[(size_t)c1 * 9216 + qa]);
            Alo[ks][3] = __float_as_uint(tl[(size_t)c1 * 9216 + qb]);
        }
    }
    float mA = -1e30f, mB = -1e30f, lA = 0.f, lB = 0.f;
    float O[8][4];
    #pragma unroll
    for (int nt = 0; nt < 8; nt++)
        #pragma unroll
        for (int u = 0; u < 4; u++) O[nt][u] = 0.f;

    const float* phb = d_phi_hi + (size_t)b * 2304 * 64;
    const float* plb = d_phi_lo + (size_t)b * 2304 * 64;
    const float* gb  = d_g     + (size_t)b * 2304 * 64;

    for (int it = 0; it < 36; it++) {
        int m0 = it * 64;
        __syncthreads();   // previous PV done before overwriting K/G
        for (int i = tid; i < 1024; i += 128) {
            int key = i >> 4, c4 = (i & 15) * 4;
            size_t src = (size_t)(m0 + key) * 64 + c4;
            *(float4*)(Khi + key * 68 + c4) = *(const float4*)(phb + src);
            *(float4*)(Klo + key * 68 + c4) = *(const float4*)(plb + src);
            *(float4*)(Gs  + key * 72 + c4) = *(const float4*)(gb  + src);
        }
        __syncthreads();
        // S = theta_tile @ phi_tile^T  (split tf32: hh + hl + lh) via LDSM fragments
        float S[8][4];
        #pragma unroll
        for (int nt = 0; nt < 8; nt++) {
            S[nt][0] = 0.f; S[nt][1] = 0.f; S[nt][2] = 0.f; S[nt][3] = 0.f;
        }
        #pragma unroll
        for (int ks = 0; ks < 8; ks++) {
            #pragma unroll
            for (int nt = 0; nt < 8; nt++) {
                uint32_t kf[4];
                ldsm4(kf, khi_base + (uint32_t)(nt * 2176 + ks * 32) + koff);
                mma_tf32(S[nt], Ahi[ks], kf[0], kf[1]);
                mma_tf32(S[nt], Ahi[ks], kf[2], kf[3]);
                mma_tf32(S[nt], Alo[ks], kf[0], kf[1]);
            }
        }
        // online softmax (logits already in log2 domain)
        float mxA = -1e30f, mxB = -1e30f;
        #pragma unroll
        for (int nt = 0; nt < 8; nt++) {
            mxA = fmaxf(mxA, fmaxf(S[nt][0], S[nt][1]));
            mxB = fmaxf(mxB, fmaxf(S[nt][2], S[nt][3]));
        }
        mxA = fmaxf(mxA, __shfl_xor_sync(0xffffffffu, mxA, 1));
        mxA = fmaxf(mxA, __shfl_xor_sync(0xffffffffu, mxA, 2));
        mxB = fmaxf(mxB, __shfl_xor_sync(0xffffffffu, mxB, 1));
        mxB = fmaxf(mxB, __shfl_xor_sync(0xffffffffu, mxB, 2));
        float mnA = fmaxf(mA, mxA), mnB = fmaxf(mB, mxB);
        float aA = ex2f(mA - mnA), aB = ex2f(mB - mnB);
        mA = mnA; mB = mnB;
        float sumA = 0.f, sumB = 0.f;
        #pragma unroll
        for (int nt = 0; nt < 8; nt++) {
            S[nt][0] = ex2f(S[nt][0] - mA);
            S[nt][1] = ex2f(S[nt][1] - mA);
            S[nt][2] = ex2f(S[nt][2] - mB);
            S[nt][3] = ex2f(S[nt][3] - mB);
            sumA += S[nt][0] + S[nt][1];
            sumB += S[nt][2] + S[nt][3];
        }
        sumA += __shfl_xor_sync(0xffffffffu, sumA, 1);
        sumA += __shfl_xor_sync(0xffffffffu, sumA, 2);
        sumB += __shfl_xor_sync(0xffffffffu, sumB, 1);
        sumB += __shfl_xor_sync(0xffffffffu, sumB, 2);
        lA = lA * aA + sumA;
        lB = lB * aB + sumB;
        #pragma unroll
        for (int nt = 0; nt < 8; nt++) {
            O[nt][0] *= aA; O[nt][1] *= aA; O[nt][2] *= aB; O[nt][3] *= aB;
        }
        // store P (tf32-rounded) to per-warp rows of Ps
        int q0 = w * 16 + g;
        #pragma unroll
        for (int nt = 0; nt < 8; nt++) {
            int k0 = nt * 8 + 2 * tig;
            *(float2*)(Ps + q0 * 68 + k0)       = make_float2(tf32r(S[nt][0]), tf32r(S[nt][1]));
            *(float2*)(Ps + (q0 + 8) * 68 + k0) = make_float2(tf32r(S[nt][2]), tf32r(S[nt][3]));
        }
        __syncwarp();   // P rows are per-warp private
        // O += P @ G   (P fragments via LDSM, G fragments scalar conflict-free)
        #pragma unroll
        for (int kt = 0; kt < 8; kt++) {
            uint32_t a[4];
            ldsm4(a, ps_base + (uint32_t)(kt * 32) + poff);
            const float* GR = Gs + (kt * 8 + tig) * 72 + g;
            #pragma unroll
            for (int nt = 0; nt < 8; nt++) {
                uint32_t b0 = __float_as_uint(GR[nt * 8]);
                uint32_t b1 = __float_as_uint(GR[4 * 72 + nt * 8]);
                mma_tf32(O[nt], a, b0, b1);
            }
        }
    }
    // normalize + transpose through smem + coalesced write to d_omap [b][c][n]
    __syncthreads();
    float ilA = 1.f / lA, ilB = 1.f / lB;
    int q0 = w * 16 + g;
    #pragma unroll
    for (int nt = 0; nt < 8; nt++) {
        int ch = nt * 8 + 2 * tig;
        Ps[ch * 68 + q0]           = O[nt][0] * ilA;
        Ps[(ch + 1) * 68 + q0]     = O[nt][1] * ilA;
        Ps[ch * 68 + q0 + 8]       = O[nt][2] * ilB;
        Ps[(ch + 1) * 68 + q0 + 8] = O[nt][3] * ilB;
    }
    __syncthreads();
    float* om = d_omap + (size_t)b * 64 * 9216 + n0;
    for (int i = tid; i < 1024; i += 128) {
        int ch = i >> 4, c4 = (i & 15) * 4;
        *(float4*)(om + (size_t)ch * 9216 + c4) = *(float4*)(Ps + ch * 68 + c4);
    }
}

// ----------------- K5: fused (o_w o up) + bias + gamma*y, coalesced out -----------------
// grid (3, 48, 16): z = b*4 + ocb ; dynamic smem 49152B
__global__ __launch_bounds__(256) void out_k(const float* __restrict__ Y,
                                             const float* __restrict__ up_b,
                                             const float* __restrict__ gammap,
                                             float* __restrict__ out) {
    extern __shared__ float sm[];
    float* Os = sm;           // [c2][px] 64*64
    float* Ws = sm + 4096;    // [c2][row] 64*128 ; later reused as 32x4x64 staging
    int tc = blockIdx.x, tr = blockIdx.y;
    int b = blockIdx.z >> 2, ocb = blockIdx.z & 3;
    int tid = threadIdx.x;
    int og = tid & 15, pg = tid >> 4;
    for (int i = tid; i < 2048; i += 256) {
        int c2 = i >> 5, r4 = i & 31;
        ((float4*)Ws)[i] = *(const float4*)(d_W2 + c2 * 512 + ocb * 128 + r4 * 4);
    }
    for (int i = tid; i < 1024; i += 256) {
        int c2 = i >> 4, s4 = i & 15;
        int r = s4 >> 3, jc = (s4 & 7) * 4;
        ((float4*)Os)[i] = *(const float4*)(d_omap + ((size_t)b * 64 + c2) * 9216
                                            + (2 * tr + r) * 96 + tc * 32 + jc);
    }
    __syncthreads();
    float acc[4][8];
    #pragma unroll
    for (int i = 0; i < 4; i++)
        #pragma unroll
        for (int u = 0; u < 8; u++) acc[i][u] = 0.f;
    #pragma unroll 4
    for (int c2 = 0; c2 < 64; c2++) {
        const float* Ar = Os + c2 * 64;
        float2 a01 = *(const float2*)(Ar + 2 * pg);
        float2 a23 = *(const float2*)(Ar + 32 + 2 * pg);
        const float* Wr = Ws + c2 * 128 + og * 8;
        float4 w0 = *(const float4*)(Wr);
        float4 w1 = *(const float4*)(Wr + 4);
        float wv[8] = {w0.x, w0.y, w0.z, w0.w, w1.x, w1.y, w1.z, w1.w};
        #pragma unroll
        for (int u = 0; u < 8; u++) {
            acc[0][u] += a01.x * wv[u];
            acc[1][u] += a01.y * wv[u];
            acc[2][u] += a23.x * wv[u];
            acc[3][u] += a23.y * wv[u];
        }
    }
    __syncthreads();
    float* stg = Ws;   // 32 oc x 4 lrow x 64 col
    #pragma unroll
    for (int u = 0; u < 8; u++) {
        int row = og * 8 + u;
        int oc_l = row >> 2, p = (row >> 1) & 1, q = row & 1;
        #pragma unroll
        for (int px = 0; px < 4; px++) {
            int r = px >> 1;
            int jc = 2 * pg + (px & 1);
            stg[oc_l * 256 + (2 * r + p) * 64 + 2 * jc + q] = acc[px][u];
        }
    }
    __syncthreads();
    float gamma = *gammap;
    for (int i = tid; i < 2048; i += 256) {
        int col4 = i & 15, lrow = (i >> 4) & 3, oc_l = i >> 6;
        int oc = ocb * 32 + oc_l;
        size_t gaddr = (((size_t)b * 128 + oc) * 192 + (4 * tr + lrow)) * 192 + tc * 64 + col4 * 4;
        float4 s = ((float4*)stg)[oc_l * 64 + lrow * 16 + col4];
        float4 yv = *(const float4*)(Y + gaddr);
        float bb = up_b[oc];
        float4 o = make_float4(s.x + bb + gamma * yv.x, s.y + bb + gamma * yv.y,
                               s.z + bb + gamma * yv.z, s.w + bb + gamma * yv.w);
        *(float4*)(out + gaddr) = o;
    }
}

// ----------------- launch -----------------
extern "C" void kernel_launch(void* const* d_in, const int* in_sizes, int n_in,
                              void* d_out, int out_size) {
    (void)in_sizes; (void)n_in; (void)out_size;
    const float* input_x = (const float*)d_in[0];
    const float* input_y = (const float*)d_in[1];
    const float* down0_w = (const float*)d_in[2];
    const float* down0_b = (const float*)d_in[3];
    const float* down1_w = (const float*)d_in[4];
    const float* down1_b = (const float*)d_in[5];
    const float* theta_w = (const float*)d_in[6];
    const float* phi_w   = (const float*)d_in[7];
    const float* g_w     = (const float*)d_in[8];
    const float* o_w     = (const float*)d_in[9];
    const float* up_w    = (const float*)d_in[10];
    const float* up_b    = (const float*)d_in[11];
    const float* gamma   = (const float*)d_in[12];
    float* out = (float*)d_out;

    cudaFuncSetAttribute(attn_tc, cudaFuncAttributeMaxDynamicSharedMemorySize, 70656);

    fuse_tp<<<64, 256>>>(theta_w, phi_w, down0_w, down0_b);
    fuse_g<<<32, 256>>>(g_w, down1_w, down1_b);
    fuse_w2<<<32, 256>>>(o_w, up_w);
    conv_tp<<<dim3(3, 24, 4), 256>>>(input_x);
    conv_g<<<dim3(3, 12, 4), 256>>>(input_y);
    attn_tc<<<dim3(144, 4), 128, 70656>>>();
    out_k<<<dim3(3, 48, 16), 256, 49152>>>(input_y, up_b, gamma, out);
}

// round 7
// speedup vs baseline: 1.3014x; 1.3014x over previous
#include <cuda_runtime.h>
#include <cuda_bf16.h>
#include <cstdint>

#define SCALE_LOGIT 7.2134752044448169f   // TEMP(5) * log2(e)

// ----------------- device scratch (no allocation allowed) -----------------
__device__ __align__(16) float d_Wtp[512 * 128];     // [k=ic*4+p*2+q][oc]; oc<64: theta(scaled), oc>=64: phi
__device__ __align__(16) float d_btp[128];           // theta bias (scaled) | phi bias
__device__ __align__(16) float d_Wg[512 * 64];       // [k][oc]
__device__ __align__(16) float d_bg[64];
__device__ __align__(16) float d_W2[64 * 512];       // [c2][oc*4+p*2+q]
__device__ __align__(16) uint32_t d_thQhi[4 * 9216 * 32];  // [b][n][c/2] packed bf16x2 hi (scaled logits)
__device__ __align__(16) uint32_t d_thQlo[4 * 9216 * 32];  // [b][n][c/2] packed bf16x2 lo
__device__ __align__(16) unsigned short d_phihi[4 * 2304 * 64]; // [b][m][c] bf16 hi (key-major)
__device__ __align__(16) unsigned short d_philo[4 * 2304 * 64]; // [b][m][c] bf16 lo
__device__ __align__(16) float d_g[4 * 2304 * 64];        // [b][m][c] tf32-rounded
__device__ __align__(16) float d_omap[4 * 64 * 9216];     // [b][c][n]

__device__ __forceinline__ float ex2f(float x) {
    float r; asm("ex2.approx.f32 %0, %1;" : "=f"(r) : "f"(x)); return r;
}
__device__ __forceinline__ float tf32r(float x) {
    uint32_t u; asm("cvt.rna.tf32.f32 %0, %1;" : "=r"(u) : "f"(x)); return __uint_as_float(u);
}
__device__ __forceinline__ void mma_tf32(float* c, const uint32_t* a, uint32_t b0, uint32_t b1) {
    asm volatile("mma.sync.aligned.m16n8k8.row.col.f32.tf32.tf32.f32 "
                 "{%0,%1,%2,%3},{%4,%5,%6,%7},{%8,%9},{%0,%1,%2,%3};"
                 : "+f"(c[0]), "+f"(c[1]), "+f"(c[2]), "+f"(c[3])
                 : "r"(a[0]), "r"(a[1]), "r"(a[2]), "r"(a[3]), "r"(b0), "r"(b1));
}
__device__ __forceinline__ void mma_bf16(float* c, const uint32_t* a, uint32_t b0, uint32_t b1) {
    asm volatile("mma.sync.aligned.m16n8k16.row.col.f32.bf16.bf16.f32 "
                 "{%0,%1,%2,%3},{%4,%5,%6,%7},{%8,%9},{%0,%1,%2,%3};"
                 : "+f"(c[0]), "+f"(c[1]), "+f"(c[2]), "+f"(c[3])
                 : "r"(a[0]), "r"(a[1]), "r"(a[2]), "r"(a[3]), "r"(b0), "r"(b1));
}
__device__ __forceinline__ void ldsm4(uint32_t* r, uint32_t addr) {
    asm volatile("ldmatrix.sync.aligned.m8n8.x4.shared.b16 {%0,%1,%2,%3}, [%4];"
                 : "=r"(r[0]), "=r"(r[1]), "=r"(r[2]), "=r"(r[3]) : "r"(addr));
}
__device__ __forceinline__ uint32_t pack_bf16x2(unsigned short lo, unsigned short hi) {
    return (uint32_t)lo | ((uint32_t)hi << 16);
}

// ----------------- K1a: fuse theta/phi with down0 -----------------
__global__ void fuse_tp(const float* __restrict__ theta_w, const float* __restrict__ phi_w,
                        const float* __restrict__ down_w, const float* __restrict__ down_b) {
    int idx = blockIdx.x * 256 + threadIdx.x;   // 16384
    int oc = idx & 127, ic = idx >> 7;
    const float* wrow = (oc < 64) ? (theta_w + oc * 128) : (phi_w + (oc - 64) * 128);
    float a0 = 0.f, a1 = 0.f, a2 = 0.f, a3 = 0.f, ab = 0.f;
    for (int c = 0; c < 128; c++) {
        float wv = wrow[c];
        float4 dv = *(const float4*)(down_w + (size_t)(c * 128 + ic) * 4);
        a0 += wv * dv.x; a1 += wv * dv.y; a2 += wv * dv.z; a3 += wv * dv.w;
        if (ic == 0) ab += wv * down_b[c];
    }
    float s = (oc < 64) ? SCALE_LOGIT : 1.f;
    d_Wtp[(ic * 4 + 0) * 128 + oc] = a0 * s;
    d_Wtp[(ic * 4 + 1) * 128 + oc] = a1 * s;
    d_Wtp[(ic * 4 + 2) * 128 + oc] = a2 * s;
    d_Wtp[(ic * 4 + 3) * 128 + oc] = a3 * s;
    if (ic == 0) d_btp[oc] = ab * s;
}

// ----------------- K1b: fuse g with down1 -----------------
__global__ void fuse_g(const float* __restrict__ g_w,
                       const float* __restrict__ down_w, const float* __restrict__ down_b) {
    int idx = blockIdx.x * 256 + threadIdx.x;   // 8192
    int oc = idx & 63, ic = idx >> 6;
    const float* wrow = g_w + oc * 128;
    float a0 = 0.f, a1 = 0.f, a2 = 0.f, a3 = 0.f, ab = 0.f;
    for (int c = 0; c < 128; c++) {
        float wv = wrow[c];
        float4 dv = *(const float4*)(down_w + (size_t)(c * 128 + ic) * 4);
        a0 += wv * dv.x; a1 += wv * dv.y; a2 += wv * dv.z; a3 += wv * dv.w;
        if (ic == 0) ab += wv * down_b[c];
    }
    d_Wg[(ic * 4 + 0) * 64 + oc] = a0;
    d_Wg[(ic * 4 + 1) * 64 + oc] = a1;
    d_Wg[(ic * 4 + 2) * 64 + oc] = a2;
    d_Wg[(ic * 4 + 3) * 64 + oc] = a3;
    if (ic == 0) d_bg[oc] = ab;
}

// ----------------- K1c: fuse o_w with up_w -----------------
__global__ void fuse_w2(const float* __restrict__ o_w, const float* __restrict__ up_w) {
    int idx = blockIdx.x * 256 + threadIdx.x;   // 8192
    int c2 = idx & 63, oc = idx >> 6;
    float a0 = 0.f, a1 = 0.f, a2 = 0.f, a3 = 0.f;
    for (int och = 0; och < 128; och++) {
        float wv = o_w[och * 64 + c2];
        float4 dv = *(const float4*)(up_w + (size_t)(och * 128 + oc) * 4);
        a0 += wv * dv.x; a1 += wv * dv.y; a2 += wv * dv.z; a3 += wv * dv.w;
    }
    d_W2[c2 * 512 + oc * 4 + 0] = a0;
    d_W2[c2 * 512 + oc * 4 + 1] = a1;
    d_W2[c2 * 512 + oc * 4 + 2] = a2;
    d_W2[c2 * 512 + oc * 4 + 3] = a3;
}

// ----------------- K2: fused theta+phi conv (2x2/s2, K=512) + phi maxpool -----------------
// grid (3, 24, 4), 256 threads; tile = 4 out-rows x 32 out-cols (128 px), 128 oc
__global__ __launch_bounds__(256) void conv_tp(const float* __restrict__ X) {
    __shared__ float As[32 * 128];   // [k_local][px = ro*32 + jc]
    __shared__ float Ws[32 * 128];   // [k_local][oc]
    int b = blockIdx.z, tr = blockIdx.y, tc = blockIdx.x;
    int tid = threadIdx.x;
    int ocg = tid & 15, pxg = tid >> 4;
    int rp = pxg >> 3, cq = pxg & 7;
    float acc[8][8];
    #pragma unroll
    for (int i = 0; i < 8; i++)
        #pragma unroll
        for (int u = 0; u < 8; u++) acc[i][u] = 0.f;
    const float* Xb = X + (size_t)b * 128 * 192 * 192;
    for (int icb = 0; icb < 16; icb++) {
        #pragma unroll
        for (int t = 0; t < 4; t++)
            ((float4*)Ws)[t * 256 + tid] = ((const float4*)(d_Wtp + icb * 4096))[t * 256 + tid];
        #pragma unroll
        for (int t = 0; t < 8; t++) {
            int i = t * 256 + tid;
            int jc = i & 31, p = (i >> 5) & 1, ro = (i >> 6) & 3, ic8 = i >> 8;
            float2 v = ((const float2*)(Xb + ((size_t)(icb * 8 + ic8) * 192
                         + 8 * tr + 2 * ro + p) * 192 + tc * 64))[jc];
            As[(ic8 * 4 + p * 2 + 0) * 128 + ro * 32 + jc] = v.x;
            As[(ic8 * 4 + p * 2 + 1) * 128 + ro * 32 + jc] = v.y;
        }
        __syncthreads();
        #pragma unroll 2
        for (int k = 0; k < 32; k++) {
            float4 alo = *(const float4*)(As + k * 128 + (2 * rp) * 32 + 4 * cq);
            float4 ahi = *(const float4*)(As + k * 128 + (2 * rp + 1) * 32 + 4 * cq);
            float4 w0 = *(const float4*)(Ws + k * 128 + ocg * 8);
            float4 w1 = *(const float4*)(Ws + k * 128 + ocg * 8 + 4);
            float av[8] = {alo.x, alo.y, alo.z, alo.w, ahi.x, ahi.y, ahi.z, ahi.w};
            float wv[8] = {w0.x, w0.y, w0.z, w0.w, w1.x, w1.y, w1.z, w1.w};
            #pragma unroll
            for (int px = 0; px < 8; px++)
                #pragma unroll
                for (int u = 0; u < 8; u++)
                    acc[px][u] += av[px] * wv[u];
        }
        __syncthreads();
    }
    if (ocg < 8) {   // theta (scaled): split-bf16, packed pairs, [b][n][32 words]
        uint32_t* qh = d_thQhi + (size_t)b * 9216 * 32;
        uint32_t* ql = d_thQlo + (size_t)b * 9216 * 32;
        float bb[8];
        #pragma unroll
        for (int u = 0; u < 8; u++) bb[u] = d_btp[ocg * 8 + u];
        #pragma unroll
        for (int px = 0; px < 8; px++) {
            int r2 = px >> 2, jj = px & 3;
            int n = (4 * tr + 2 * rp + r2) * 96 + tc * 32 + 4 * cq + jj;
            #pragma unroll
            for (int uu = 0; uu < 4; uu++) {
                float v0 = acc[px][2 * uu] + bb[2 * uu];
                float v1 = acc[px][2 * uu + 1] + bb[2 * uu + 1];
                __nv_bfloat16 h0 = __float2bfloat16_rn(v0);
                __nv_bfloat16 h1 = __float2bfloat16_rn(v1);
                __nv_bfloat16 l0 = __float2bfloat16_rn(v0 - __bfloat162float(h0));
                __nv_bfloat16 l1 = __float2bfloat16_rn(v1 - __bfloat162float(h1));
                size_t w = (size_t)n * 32 + ocg * 4 + uu;
                qh[w] = pack_bf16x2(__bfloat16_as_ushort(h0), __bfloat16_as_ushort(h1));
                ql[w] = pack_bf16x2(__bfloat16_as_ushort(l0), __bfloat16_as_ushort(l1));
            }
        }
    } else {         // phi, maxpooled 2x2: split-bf16, key-major [b][m][c]
        #pragma unroll
        for (int u = 0; u < 8; u++) {
            int c = (ocg - 8) * 8 + u;
            float bv = d_btp[64 + c];
            int m0 = (2 * tr + rp) * 48 + tc * 16 + 2 * cq;
            float p0 = fmaxf(fmaxf(acc[0][u], acc[1][u]), fmaxf(acc[4][u], acc[5][u])) + bv;
            float p1 = fmaxf(fmaxf(acc[2][u], acc[3][u]), fmaxf(acc[6][u], acc[7][u])) + bv;
            __nv_bfloat16 h0 = __float2bfloat16_rn(p0);
            __nv_bfloat16 h1 = __float2bfloat16_rn(p1);
            __nv_bfloat16 l0 = __float2bfloat16_rn(p0 - __bfloat162float(h0));
            __nv_bfloat16 l1 = __float2bfloat16_rn(p1 - __bfloat162float(h1));
            size_t a0 = ((size_t)b * 2304 + m0) * 64 + c;
            d_phihi[a0]      = __bfloat16_as_ushort(h0);
            d_philo[a0]      = __bfloat16_as_ushort(l0);
            d_phihi[a0 + 64] = __bfloat16_as_ushort(h1);
            d_philo[a0 + 64] = __bfloat16_as_ushort(l1);
        }
    }
}

// ----------------- K3: fused g conv (2x2/s2, K=512) + maxpool -----------------
// grid (3, 24, 4), 128 threads; tile = 4 out-rows x 32 out-cols (128 px), 64 oc
__global__ __launch_bounds__(128) void conv_g(const float* __restrict__ Y) {
    __shared__ float As[32 * 128];
    __shared__ float Ws[32 * 64];
    int b = blockIdx.z, tr = blockIdx.y, tc = blockIdx.x;
    int tid = threadIdx.x;
    int ocg = tid & 7, pxg = tid >> 3;
    int rp = pxg >> 3, cq = pxg & 7;
    float acc[8][8];
    #pragma unroll
    for (int i = 0; i < 8; i++)
        #pragma unroll
        for (int u = 0; u < 8; u++) acc[i][u] = 0.f;
    const float* Yb = Y + (size_t)b * 128 * 192 * 192;
    for (int icb = 0; icb < 16; icb++) {
        #pragma unroll
        for (int t = 0; t < 4; t++)
            ((float4*)Ws)[t * 128 + tid] = ((const float4*)(d_Wg + icb * 2048))[t * 128 + tid];
        #pragma unroll
        for (int t = 0; t < 16; t++) {
            int i = t * 128 + tid;
            int jc = i & 31, p = (i >> 5) & 1, ro = (i >> 6) & 3, ic8 = i >> 8;
            float2 v = ((const float2*)(Yb + ((size_t)(icb * 8 + ic8) * 192
                         + 8 * tr + 2 * ro + p) * 192 + tc * 64))[jc];
            As[(ic8 * 4 + p * 2 + 0) * 128 + ro * 32 + jc] = v.x;
            As[(ic8 * 4 + p * 2 + 1) * 128 + ro * 32 + jc] = v.y;
        }
        __syncthreads();
        #pragma unroll 2
        for (int k = 0; k < 32; k++) {
            float4 alo = *(const float4*)(As + k * 128 + (2 * rp) * 32 + 4 * cq);
            float4 ahi = *(const float4*)(As + k * 128 + (2 * rp + 1) * 32 + 4 * cq);
            float4 w0 = *(const float4*)(Ws + k * 64 + ocg * 8);
            float4 w1 = *(const float4*)(Ws + k * 64 + ocg * 8 + 4);
            float av[8] = {alo.x, alo.y, alo.z, alo.w, ahi.x, ahi.y, ahi.z, ahi.w};
            float wv[8] = {w0.x, w0.y, w0.z, w0.w, w1.x, w1.y, w1.z, w1.w};
            #pragma unroll
            for (int px = 0; px < 8; px++)
                #pragma unroll
                for (int u = 0; u < 8; u++)
                    acc[px][u] += av[px] * wv[u];
        }
        __syncthreads();
    }
    int m0 = (2 * tr + rp) * 48 + tc * 16 + 2 * cq;   // pooled
    float r0[8], r1[8];
    #pragma unroll
    for (int u = 0; u < 8; u++) {
        float bv = d_bg[ocg * 8 + u];
        r0[u] = tf32r(fmaxf(fmaxf(acc[0][u], acc[1][u]), fmaxf(acc[4][u], acc[5][u])) + bv);
        r1[u] = tf32r(fmaxf(fmaxf(acc[2][u], acc[3][u]), fmaxf(acc[6][u], acc[7][u])) + bv);
    }
    float* g0 = d_g + ((size_t)b * 2304 + m0) * 64 + ocg * 8;
    *(float4*)(g0)      = make_float4(r0[0], r0[1], r0[2], r0[3]);
    *(float4*)(g0 + 4)  = make_float4(r0[4], r0[5], r0[6], r0[7]);
    *(float4*)(g0 + 64) = make_float4(r1[0], r1[1], r1[2], r1[3]);
    *(float4*)(g0 + 68) = make_float4(r1[4], r1[5], r1[6], r1[7]);
}

// ----------------- K4: flash attention, bf16-split QK + tf32 PV (Br=64, Bc=64, C=64) -----------------
// grid (144, 4), 128 threads (4 warps, one m16 q-row tile each)
// smem (bytes): Khi[64x72 bf16]@0 (9216), Klo@9216 (9216), Gs[64x72 f32]@18432 (18432), Ps[64x68 f32]@36864 (17408)
__global__ __launch_bounds__(128) void attn_tc() {
    extern __shared__ float sm[];
    uint32_t* KhiW = (uint32_t*)sm;                 // [64 key][36 words] (72 bf16)
    uint32_t* KloW = (uint32_t*)sm + 2304;
    float* Gs = sm + 4608;                          // [64 key][72 f32]
    float* Ps = sm + 4608 + 4608;                   // [64 q][68 f32]
    int b = blockIdx.y;
    int n0 = blockIdx.x * 64;
    int tid = threadIdx.x;
    int w = tid >> 5, lane = tid & 31;
    int g = lane >> 2, tig = lane & 3;
    int qa = n0 + w * 16 + g, qb = qa + 8;

    uint32_t sm_u32 = (uint32_t)__cvta_generic_to_shared(sm);
    uint32_t k_base = sm_u32;
    uint32_t ps_base = sm_u32 + 36864;
    int lr = lane & 7, sel = lane >> 3;
    // K LDSM per-lane offset: mats = {Khi b0, Khi b1, Klo b0, Klo b1}; row stride 144B
    uint32_t koff = (uint32_t)(lr * 144 + (sel & 1) * 16 + ((sel >> 1) ? 9216 : 0));
    // P LDSM per-lane offset (tf32 A-frag): row stride 272B
    uint32_t poff = (uint32_t)(((lane & 7) + (sel & 1) * 8) * 272 + (sel >> 1) * 16)
                    + (uint32_t)(w * 16 * 272);

    // Q fragments: 4 k16-steps, hi & lo packed bf16x2
    uint32_t Qhi[4][4], Qlo[4][4];
    {
        const uint32_t* qh = d_thQhi + (size_t)b * 9216 * 32;
        const uint32_t* ql = d_thQlo + (size_t)b * 9216 * 32;
        #pragma unroll
        for (int ks = 0; ks < 4; ks++) {
            Qhi[ks][0] = qh[(size_t)qa * 32 + ks * 8 + tig];
            Qhi[ks][1] = qh[(size_t)qb * 32 + ks * 8 + tig];
            Qhi[ks][2] = qh[(size_t)qa * 32 + ks * 8 + tig + 4];
            Qhi[ks][3] = qh[(size_t)qb * 32 + ks * 8 + tig + 4];
            Qlo[ks][0] = ql[(size_t)qa * 32 + ks * 8 + tig];
            Qlo[ks][1] = ql[(size_t)qb * 32 + ks * 8 + tig];
            Qlo[ks][2] = ql[(size_t)qa * 32 + ks * 8 + tig + 4];
            Qlo[ks][3] = ql[(size_t)qb * 32 + ks * 8 + tig + 4];
        }
    }
    float mA = -1e30f, mB = -1e30f, lA = 0.f, lB = 0.f;
    float O[8][4];
    #pragma unroll
    for (int nt = 0; nt < 8; nt++)
        #pragma unroll
        for (int u = 0; u < 4; u++) O[nt][u] = 0.f;

    const uint32_t* phw = (const uint32_t*)d_phihi + (size_t)b * 2304 * 32;
    const uint32_t* plw = (const uint32_t*)d_philo + (size_t)b * 2304 * 32;
    const float* gb = d_g + (size_t)b * 2304 * 64;

    for (int it = 0; it < 36; it++) {
        int m0 = it * 64;
        __syncthreads();
        #pragma unroll
        for (int t = 0; t < 16; t++) {   // K hi+lo: 2048 words each... 4096 total / 128 = 32; here 16 iters x 2
            int i = t * 128 + tid;
            int key = i >> 5, wd = i & 31;
            KhiW[key * 36 + wd] = phw[(size_t)(m0 + key) * 32 + wd];
            KloW[key * 36 + wd] = plw[(size_t)(m0 + key) * 32 + wd];
        }
        #pragma unroll
        for (int t = 0; t < 8; t++) {    // G: 1024 float4 / 128 = 8
            int i = t * 128 + tid;
            int key = i >> 4, c4 = (i & 15) * 4;
            *(float4*)(Gs + key * 72 + c4) = *(const float4*)(gb + (size_t)(m0 + key) * 64 + c4);
        }
        __syncthreads();
        // S = theta @ phi^T : split-bf16 (hh + hl + lh), m16n8k16
        float S[8][4];
        #pragma unroll
        for (int nt = 0; nt < 8; nt++) {
            S[nt][0] = 0.f; S[nt][1] = 0.f; S[nt][2] = 0.f; S[nt][3] = 0.f;
        }
        #pragma unroll
        for (int ks = 0; ks < 4; ks++) {
            #pragma unroll
            for (int nt = 0; nt < 8; nt++) {
                uint32_t kf[4];
                ldsm4(kf, k_base + (uint32_t)(nt * 1152 + ks * 32) + koff);
                mma_bf16(S[nt], Qhi[ks], kf[0], kf[1]);
                mma_bf16(S[nt], Qhi[ks], kf[2], kf[3]);
                mma_bf16(S[nt], Qlo[ks], kf[0], kf[1]);
            }
        }
        // online softmax (logits in log2 domain)
        float mxA = -1e30f, mxB = -1e30f;
        #pragma unroll
        for (int nt = 0; nt < 8; nt++) {
            mxA = fmaxf(mxA, fmaxf(S[nt][0], S[nt][1]));
            mxB = fmaxf(mxB, fmaxf(S[nt][2], S[nt][3]));
        }
        mxA = fmaxf(mxA, __shfl_xor_sync(0xffffffffu, mxA, 1));
        mxA = fmaxf(mxA, __shfl_xor_sync(0xffffffffu, mxA, 2));
        mxB = fmaxf(mxB, __shfl_xor_sync(0xffffffffu, mxB, 1));
        mxB = fmaxf(mxB, __shfl_xor_sync(0xffffffffu, mxB, 2));
        float mnA = fmaxf(mA, mxA), mnB = fmaxf(mB, mxB);
        float aA = ex2f(mA - mnA), aB = ex2f(mB - mnB);
        mA = mnA; mB = mnB;
        float sumA = 0.f, sumB = 0.f;
        #pragma unroll
        for (int nt = 0; nt < 8; nt++) {
            S[nt][0] = ex2f(S[nt][0] - mA);
            S[nt][1] = ex2f(S[nt][1] - mA);
            S[nt][2] = ex2f(S[nt][2] - mB);
            S[nt][3] = ex2f(S[nt][3] - mB);
            sumA += S[nt][0] + S[nt][1];
            sumB += S[nt][2] + S[nt][3];
        }
        sumA += __shfl_xor_sync(0xffffffffu, sumA, 1);
        sumA += __shfl_xor_sync(0xffffffffu, sumA, 2);
        sumB += __shfl_xor_sync(0xffffffffu, sumB, 1);
        sumB += __shfl_xor_sync(0xffffffffu, sumB, 2);
        lA = lA * aA + sumA;
        lB = lB * aB + sumB;
        #pragma unroll
        for (int nt = 0; nt < 8; nt++) {
            O[nt][0] *= aA; O[nt][1] *= aA; O[nt][2] *= aB; O[nt][3] *= aB;
        }
        // store P (tf32-rounded) to per-warp rows of Ps
        int q0 = w * 16 + g;
        #pragma unroll
        for (int nt = 0; nt < 8; nt++) {
            int k0 = nt * 8 + 2 * tig;
            *(float2*)(Ps + q0 * 68 + k0)       = make_float2(tf32r(S[nt][0]), tf32r(S[nt][1]));
            *(float2*)(Ps + (q0 + 8) * 68 + k0) = make_float2(tf32r(S[nt][2]), tf32r(S[nt][3]));
        }
        __syncwarp();
        // O += P @ G   (tf32; P frags via LDSM, G scalar conflict-free)
        #pragma unroll
        for (int kt = 0; kt < 8; kt++) {
            uint32_t a[4];
            ldsm4(a, ps_base + (uint32_t)(kt * 32) + poff);
            const float* GR = Gs + (kt * 8 + tig) * 72 + g;
            #pragma unroll
            for (int nt = 0; nt < 8; nt++) {
                uint32_t b0 = __float_as_uint(GR[nt * 8]);
                uint32_t b1 = __float_as_uint(GR[4 * 72 + nt * 8]);
                mma_tf32(O[nt], a, b0, b1);
            }
        }
    }
    // normalize + transpose through smem + coalesced write to d_omap [b][c][n]
    __syncthreads();
    float ilA = 1.f / lA, ilB = 1.f / lB;
    int q0 = w * 16 + g;
    #pragma unroll
    for (int nt = 0; nt < 8; nt++) {
        int ch = nt * 8 + 2 * tig;
        Ps[ch * 68 + q0]           = O[nt][0] * ilA;
        Ps[(ch + 1) * 68 + q0]     = O[nt][1] * ilA;
        Ps[ch * 68 + q0 + 8]       = O[nt][2] * ilB;
        Ps[(ch + 1) * 68 + q0 + 8] = O[nt][3] * ilB;
    }
    __syncthreads();
    float* om = d_omap + (size_t)b * 64 * 9216 + n0;
    for (int i = tid; i < 1024; i += 128) {
        int ch = i >> 4, c4 = (i & 15) * 4;
        *(float4*)(om + (size_t)ch * 9216 + c4) = *(float4*)(Ps + ch * 68 + c4);
    }
}

// ----------------- K5: fused (o_w o up) + bias + gamma*y, coalesced out -----------------
// grid (3, 48, 16): z = b*4 + ocb ; dynamic smem 49152B
__global__ __launch_bounds__(256) void out_k(const float* __restrict__ Y,
                                             const float* __restrict__ up_b,
                                             const float* __restrict__ gammap,
                                             float* __restrict__ out) {
    extern __shared__ float sm[];
    float* Os = sm;           // [c2][px] 64*64
    float* Ws = sm + 4096;    // [c2][row] 64*128 ; later reused as 32x4x64 staging
    int tc = blockIdx.x, tr = blockIdx.y;
    int b = blockIdx.z >> 2, ocb = blockIdx.z & 3;
    int tid = threadIdx.x;
    int og = tid & 15, pg = tid >> 4;
    for (int i = tid; i < 2048; i += 256) {
        int c2 = i >> 5, r4 = i & 31;
        ((float4*)Ws)[i] = *(const float4*)(d_W2 + c2 * 512 + ocb * 128 + r4 * 4);
    }
    for (int i = tid; i < 1024; i += 256) {
        int c2 = i >> 4, s4 = i & 15;
        int r = s4 >> 3, jc = (s4 & 7) * 4;
        ((float4*)Os)[i] = *(const float4*)(d_omap + ((size_t)b * 64 + c2) * 9216
                                            + (2 * tr + r) * 96 + tc * 32 + jc);
    }
    __syncthreads();
    float acc[4][8];
    #pragma unroll
    for (int i = 0; i < 4; i++)
        #pragma unroll
        for (int u = 0; u < 8; u++) acc[i][u] = 0.f;
    #pragma unroll 4
    for (int c2 = 0; c2 < 64; c2++) {
        const float* Ar = Os + c2 * 64;
        float2 a01 = *(const float2*)(Ar + 2 * pg);
        float2 a23 = *(const float2*)(Ar + 32 + 2 * pg);
        const float* Wr = Ws + c2 * 128 + og * 8;
        float4 w0 = *(const float4*)(Wr);
        float4 w1 = *(const float4*)(Wr + 4);
        float wv[8] = {w0.x, w0.y, w0.z, w0.w, w1.x, w1.y, w1.z, w1.w};
        #pragma unroll
        for (int u = 0; u < 8; u++) {
            acc[0][u] += a01.x * wv[u];
            acc[1][u] += a01.y * wv[u];
            acc[2][u] += a23.x * wv[u];
            acc[3][u] += a23.y * wv[u];
        }
    }
    __syncthreads();
    float* stg = Ws;   // 32 oc x 4 lrow x 64 col
    #pragma unroll
    for (int u = 0; u < 8; u++) {
        int row = og * 8 + u;
        int oc_l = row >> 2, p = (row >> 1) & 1, q = row & 1;
        #pragma unroll
        for (int px = 0; px < 4; px++) {
            int r = px >> 1;
            int jc = 2 * pg + (px & 1);
            stg[oc_l * 256 + (2 * r + p) * 64 + 2 * jc + q] = acc[px][u];
        }
    }
    __syncthreads();
    float gamma = *gammap;
    for (int i = tid; i < 2048; i += 256) {
        int col4 = i & 15, lrow = (i >> 4) & 3, oc_l = i >> 6;
        int oc = ocb * 32 + oc_l;
        size_t gaddr = (((size_t)b * 128 + oc) * 192 + (4 * tr + lrow)) * 192 + tc * 64 + col4 * 4;
        float4 s = ((float4*)stg)[oc_l * 64 + lrow * 16 + col4];
        float4 yv = *(const float4*)(Y + gaddr);
        float bb = up_b[oc];
        float4 o = make_float4(s.x + bb + gamma * yv.x, s.y + bb + gamma * yv.y,
                               s.z + bb + gamma * yv.z, s.w + bb + gamma * yv.w);
        *(float4*)(out + gaddr) = o;
    }
}

// ----------------- launch -----------------
extern "C" void kernel_launch(void* const* d_in, const int* in_sizes, int n_in,
                              void* d_out, int out_size) {
    (void)in_sizes; (void)n_in; (void)out_size;
    const float* input_x = (const float*)d_in[0];
    const float* input_y = (const float*)d_in[1];
    const float* down0_w = (const float*)d_in[2];
    const float* down0_b = (const float*)d_in[3];
    const float* down1_w = (const float*)d_in[4];
    const float* down1_b = (const float*)d_in[5];
    const float* theta_w = (const float*)d_in[6];
    const float* phi_w   = (const float*)d_in[7];
    const float* g_w     = (const float*)d_in[8];
    const float* o_w     = (const float*)d_in[9];
    const float* up_w    = (const float*)d_in[10];
    const float* up_b    = (const float*)d_in[11];
    const float* gamma   = (const float*)d_in[12];
    float* out = (float*)d_out;

    cudaFuncSetAttribute(attn_tc, cudaFuncAttributeMaxDynamicSharedMemorySize, 54272);

    fuse_tp<<<64, 256>>>(theta_w, phi_w, down0_w, down0_b);
    fuse_g<<<32, 256>>>(g_w, down1_w, down1_b);
    fuse_w2<<<32, 256>>>(o_w, up_w);
    conv_tp<<<dim3(3, 24, 4), 256>>>(input_x);
    conv_g<<<dim3(3, 24, 4), 128>>>(input_y);
    attn_tc<<<dim3(144, 4), 128, 54272>>>();
    out_k<<<dim3(3, 48, 16), 256, 49152>>>(input_y, up_b, gamma, out);
}

// round 9
// speedup vs baseline: 1.3048x; 1.0026x over previous
#include <cuda_runtime.h>
#include <cuda_bf16.h>
#include <cuda_fp16.h>
#include <cstdint>

#define SCALE_LOGIT 7.2134752044448169f   // TEMP(5) * log2(e)

// ----------------- device scratch (no allocation allowed) -----------------
__device__ __align__(16) float d_Wtp[512 * 128];     // [k=ic*4+p*2+q][oc]; oc<64: theta(scaled), oc>=64: phi
__device__ __align__(16) float d_btp[128];           // theta bias (scaled) | phi bias
__device__ __align__(16) float d_Wg[512 * 64];       // [k][oc]
__device__ __align__(16) float d_bg[64];
__device__ __align__(16) float d_W2[64 * 512];       // [c2][oc*4+p*2+q]
__device__ __align__(16) uint32_t d_thQhi[4 * 9216 * 32];  // [b][n][c/2] packed bf16x2 hi (scaled logits)
__device__ __align__(16) uint32_t d_thQlo[4 * 9216 * 32];  // [b][n][c/2] packed bf16x2 lo
__device__ __align__(16) unsigned short d_phihi[4 * 2304 * 64]; // [b][m][c] bf16 hi (key-major)
__device__ __align__(16) unsigned short d_philo[4 * 2304 * 64]; // [b][m][c] bf16 lo
__device__ __align__(16) uint32_t d_g2[4 * 1152 * 64];    // [b][m/2][c] half2(g[2m],g[2m+1])
__device__ __align__(16) float d_omap[4 * 64 * 9216];     // [b][c][n]

__device__ __forceinline__ float ex2f(float x) {
    float r; asm("ex2.approx.f32 %0, %1;" : "=f"(r) : "f"(x)); return r;
}
__device__ __forceinline__ void mma_bf16(float* c, const uint32_t* a, uint32_t b0, uint32_t b1) {
    asm volatile("mma.sync.aligned.m16n8k16.row.col.f32.bf16.bf16.f32 "
                 "{%0,%1,%2,%3},{%4,%5,%6,%7},{%8,%9},{%0,%1,%2,%3};"
                 : "+f"(c[0]), "+f"(c[1]), "+f"(c[2]), "+f"(c[3])
                 : "r"(a[0]), "r"(a[1]), "r"(a[2]), "r"(a[3]), "r"(b0), "r"(b1));
}
__device__ __forceinline__ void mma_fp16(float* c, const uint32_t* a, uint32_t b0, uint32_t b1) {
    asm volatile("mma.sync.aligned.m16n8k16.row.col.f32.f16.f16.f32 "
                 "{%0,%1,%2,%3},{%4,%5,%6,%7},{%8,%9},{%0,%1,%2,%3};"
                 : "+f"(c[0]), "+f"(c[1]), "+f"(c[2]), "+f"(c[3])
                 : "r"(a[0]), "r"(a[1]), "r"(a[2]), "r"(a[3]), "r"(b0), "r"(b1));
}
__device__ __forceinline__ void ldsm4(uint32_t* r, uint32_t addr) {
    asm volatile("ldmatrix.sync.aligned.m8n8.x4.shared.b16 {%0,%1,%2,%3}, [%4];"
                 : "=r"(r[0]), "=r"(r[1]), "=r"(r[2]), "=r"(r[3]) : "r"(addr));
}
__device__ __forceinline__ uint32_t pack_bf16x2(unsigned short lo, unsigned short hi) {
    return (uint32_t)lo | ((uint32_t)hi << 16);
}
__device__ __forceinline__ void cp16(uint32_t dst, const void* src) {
    asm volatile("cp.async.cg.shared.global [%0], [%1], 16;" :: "r"(dst), "l"(src));
}
__device__ __forceinline__ void cp_commit() { asm volatile("cp.async.commit_group;"); }

// ----------------- K1a: fuse theta/phi with down0 -----------------
__global__ void fuse_tp(const float* __restrict__ theta_w, const float* __restrict__ phi_w,
                        const float* __restrict__ down_w, const float* __restrict__ down_b) {
    int idx = blockIdx.x * 256 + threadIdx.x;   // 16384
    int oc = idx & 127, ic = idx >> 7;
    const float* wrow = (oc < 64) ? (theta_w + oc * 128) : (phi_w + (oc - 64) * 128);
    float a0 = 0.f, a1 = 0.f, a2 = 0.f, a3 = 0.f, ab = 0.f;
    for (int c = 0; c < 128; c++) {
        float wv = wrow[c];
        float4 dv = *(const float4*)(down_w + (size_t)(c * 128 + ic) * 4);
        a0 += wv * dv.x; a1 += wv * dv.y; a2 += wv * dv.z; a3 += wv * dv.w;
        if (ic == 0) ab += wv * down_b[c];
    }
    float s = (oc < 64) ? SCALE_LOGIT : 1.f;
    d_Wtp[(ic * 4 + 0) * 128 + oc] = a0 * s;
    d_Wtp[(ic * 4 + 1) * 128 + oc] = a1 * s;
    d_Wtp[(ic * 4 + 2) * 128 + oc] = a2 * s;
    d_Wtp[(ic * 4 + 3) * 128 + oc] = a3 * s;
    if (ic == 0) d_btp[oc] = ab * s;
}

// ----------------- K1b: fuse g with down1 -----------------
__global__ void fuse_g(const float* __restrict__ g_w,
                       const float* __restrict__ down_w, const float* __restrict__ down_b) {
    int idx = blockIdx.x * 256 + threadIdx.x;   // 8192
    int oc = idx & 63, ic = idx >> 6;
    const float* wrow = g_w + oc * 128;
    float a0 = 0.f, a1 = 0.f, a2 = 0.f, a3 = 0.f, ab = 0.f;
    for (int c = 0; c < 128; c++) {
        float wv = wrow[c];
        float4 dv = *(const float4*)(down_w + (size_t)(c * 128 + ic) * 4);
        a0 += wv * dv.x; a1 += wv * dv.y; a2 += wv * dv.z; a3 += wv * dv.w;
        if (ic == 0) ab += wv * down_b[c];
    }
    d_Wg[(ic * 4 + 0) * 64 + oc] = a0;
    d_Wg[(ic * 4 + 1) * 64 + oc] = a1;
    d_Wg[(ic * 4 + 2) * 64 + oc] = a2;
    d_Wg[(ic * 4 + 3) * 64 + oc] = a3;
    if (ic == 0) d_bg[oc] = ab;
}

// ----------------- K1c: fuse o_w with up_w -----------------
__global__ void fuse_w2(const float* __restrict__ o_w, const float* __restrict__ up_w) {
    int idx = blockIdx.x * 256 + threadIdx.x;   // 8192
    int c2 = idx & 63, oc = idx >> 6;
    float a0 = 0.f, a1 = 0.f, a2 = 0.f, a3 = 0.f;
    for (int och = 0; och < 128; och++) {
        float wv = o_w[och * 64 + c2];
        float4 dv = *(const float4*)(up_w + (size_t)(och * 128 + oc) * 4);
        a0 += wv * dv.x; a1 += wv * dv.y; a2 += wv * dv.z; a3 += wv * dv.w;
    }
    d_W2[c2 * 512 + oc * 4 + 0] = a0;
    d_W2[c2 * 512 + oc * 4 + 1] = a1;
    d_W2[c2 * 512 + oc * 4 + 2] = a2;
    d_W2[c2 * 512 + oc * 4 + 3] = a3;
}

// ----------------- K2: fused theta+phi conv, cp.async double-buffered -----------------
// grid (3, 24, 4), 256 threads; tile = 4 out-rows x 32 out-cols (128 px), 128 oc
// dyn smem 64KB: Araw[2][64 rows][64 f]  Ws[2][32 k][128 oc]
__global__ __launch_bounds__(256) void conv_tp(const float* __restrict__ X) {
    extern __shared__ float smf[];
    float* Araw = smf;              // 2 x 4096 floats
    float* Ws   = smf + 8192;       // 2 x 4096 floats
    uint32_t araw_u = (uint32_t)__cvta_generic_to_shared(Araw);
    uint32_t ws_u   = (uint32_t)__cvta_generic_to_shared(Ws);
    int b = blockIdx.z, tr = blockIdx.y, tc = blockIdx.x;
    int tid = threadIdx.x;
    int ocg = tid & 15, pxg = tid >> 4;
    int rp = pxg >> 3, cq = pxg & 7;
    float acc[8][8];
    #pragma unroll
    for (int i = 0; i < 8; i++)
        #pragma unroll
        for (int u = 0; u < 8; u++) acc[i][u] = 0.f;
    const float* Xb = X + (size_t)b * 128 * 192 * 192;

    auto issue = [&](int icb, int buf) {
        const float4* wsrc = (const float4*)(d_Wtp + icb * 4096);
        uint32_t wdst = ws_u + buf * 16384;
        #pragma unroll
        for (int t = 0; t < 4; t++)
            cp16(wdst + (t * 256 + tid) * 16, wsrc + t * 256 + tid);
        // A tile: 64 rows x 256 B = 1024 x 16B chunks
        #pragma unroll
        for (int t = 0; t < 4; t++) {
            int i = t * 256 + tid;
            int row = i >> 4, seg = i & 15;
            int ic8 = row >> 3, ro = (row >> 1) & 3, p = row & 1;
            const float* asrc = Xb + ((size_t)(icb * 8 + ic8) * 192 + 8 * tr + 2 * ro + p) * 192
                                + tc * 64 + seg * 4;
            cp16(araw_u + buf * 16384 + row * 256 + seg * 16, asrc);
        }
        cp_commit();
    };

    issue(0, 0);
    for (int icb = 0; icb < 16; icb++) {
        int buf = icb & 1;
        if (icb < 15) {
            issue(icb + 1, buf ^ 1);
            asm volatile("cp.async.wait_group 1;");
        } else {
            asm volatile("cp.async.wait_group 0;");
        }
        __syncthreads();
        const float* A = Araw + buf * 4096;
        const float* W = Ws + buf * 4096;
        #pragma unroll 2
        for (int ko = 0; ko < 16; ko++) {
            int ic8 = ko >> 1, p = ko & 1;
            const float* r0 = A + (ic8 * 8 + 4 * rp + p) * 64 + 8 * cq;
            float4 A00 = *(const float4*)(r0);
            float4 A01 = *(const float4*)(r0 + 4);
            float4 A10 = *(const float4*)(r0 + 128);
            float4 A11 = *(const float4*)(r0 + 132);
            const float* wp = W + (ic8 * 4 + p * 2) * 128 + ocg * 8;
            float4 wq0a = *(const float4*)(wp);
            float4 wq0b = *(const float4*)(wp + 4);
            float4 wq1a = *(const float4*)(wp + 128);
            float4 wq1b = *(const float4*)(wp + 132);
            float w0[8] = {wq0a.x, wq0a.y, wq0a.z, wq0a.w, wq0b.x, wq0b.y, wq0b.z, wq0b.w};
            float w1[8] = {wq1a.x, wq1a.y, wq1a.z, wq1a.w, wq1b.x, wq1b.y, wq1b.z, wq1b.w};
            #pragma unroll
            for (int u = 0; u < 8; u++) {
                acc[0][u] += A00.x * w0[u] + A00.y * w1[u];
                acc[1][u] += A00.z * w0[u] + A00.w * w1[u];
                acc[2][u] += A01.x * w0[u] + A01.y * w1[u];
                acc[3][u] += A01.z * w0[u] + A01.w * w1[u];
                acc[4][u] += A10.x * w0[u] + A10.y * w1[u];
                acc[5][u] += A10.z * w0[u] + A10.w * w1[u];
                acc[6][u] += A11.x * w0[u] + A11.y * w1[u];
                acc[7][u] += A11.z * w0[u] + A11.w * w1[u];
            }
        }
        __syncthreads();
    }
    if (ocg < 8) {   // theta (scaled): split-bf16, packed pairs, [b][n][32 words]
        uint32_t* qh = d_thQhi + (size_t)b * 9216 * 32;
        uint32_t* ql = d_thQlo + (size_t)b * 9216 * 32;
        float bb[8];
        #pragma unroll
        for (int u = 0; u < 8; u++) bb[u] = d_btp[ocg * 8 + u];
        #pragma unroll
        for (int px = 0; px < 8; px++) {
            int r2 = px >> 2, jj = px & 3;
            int n = (4 * tr + 2 * rp + r2) * 96 + tc * 32 + 4 * cq + jj;
            #pragma unroll
            for (int uu = 0; uu < 4; uu++) {
                float v0 = acc[px][2 * uu] + bb[2 * uu];
                float v1 = acc[px][2 * uu + 1] + bb[2 * uu + 1];
                __nv_bfloat16 h0 = __float2bfloat16_rn(v0);
                __nv_bfloat16 h1 = __float2bfloat16_rn(v1);
                __nv_bfloat16 l0 = __float2bfloat16_rn(v0 - __bfloat162float(h0));
                __nv_bfloat16 l1 = __float2bfloat16_rn(v1 - __bfloat162float(h1));
                size_t w = (size_t)n * 32 + ocg * 4 + uu;
                qh[w] = pack_bf16x2(__bfloat16_as_ushort(h0), __bfloat16_as_ushort(h1));
                ql[w] = pack_bf16x2(__bfloat16_as_ushort(l0), __bfloat16_as_ushort(l1));
            }
        }
    } else {         // phi, maxpooled 2x2: split-bf16, key-major [b][m][c]
        #pragma unroll
        for (int u = 0; u < 8; u++) {
            int c = (ocg - 8) * 8 + u;
            float bv = d_btp[64 + c];
            int m0 = (2 * tr + rp) * 48 + tc * 16 + 2 * cq;
            float p0 = fmaxf(fmaxf(acc[0][u], acc[1][u]), fmaxf(acc[4][u], acc[5][u])) + bv;
            float p1 = fmaxf(fmaxf(acc[2][u], acc[3][u]), fmaxf(acc[6][u], acc[7][u])) + bv;
            __nv_bfloat16 h0 = __float2bfloat16_rn(p0);
            __nv_bfloat16 h1 = __float2bfloat16_rn(p1);
            __nv_bfloat16 l0 = __float2bfloat16_rn(p0 - __bfloat162float(h0));
            __nv_bfloat16 l1 = __float2bfloat16_rn(p1 - __bfloat162float(h1));
            size_t a0 = ((size_t)b * 2304 + m0) * 64 + c;
            d_phihi[a0]      = __bfloat16_as_ushort(h0);
            d_philo[a0]      = __bfloat16_as_ushort(l0);
            d_phihi[a0 + 64] = __bfloat16_as_ushort(h1);
            d_philo[a0 + 64] = __bfloat16_as_ushort(l1);
        }
    }
}

// ----------------- K3: fused g conv + maxpool, cp.async double-buffered -----------------
// grid (3, 24, 4), 128 threads; tile = 4 out-rows x 32 out-cols (128 px), 64 oc
// dyn smem 48KB: Araw[2][64][64]  Ws[2][32][64]
__global__ __launch_bounds__(128) void conv_g(const float* __restrict__ Y) {
    extern __shared__ float smf[];
    float* Araw = smf;              // 2 x 4096
    float* Ws   = smf + 8192;       // 2 x 2048
    uint32_t araw_u = (uint32_t)__cvta_generic_to_shared(Araw);
    uint32_t ws_u   = (uint32_t)__cvta_generic_to_shared(Ws);
    int b = blockIdx.z, tr = blockIdx.y, tc = blockIdx.x;
    int tid = threadIdx.x;
    int ocg = tid & 7, pxg = tid >> 3;
    int rp = pxg >> 3, cq = pxg & 7;
    float acc[8][8];
    #pragma unroll
    for (int i = 0; i < 8; i++)
        #pragma unroll
        for (int u = 0; u < 8; u++) acc[i][u] = 0.f;
    const float* Yb = Y + (size_t)b * 128 * 192 * 192;

    auto issue = [&](int icb, int buf) {
        const float4* wsrc = (const float4*)(d_Wg + icb * 2048);
        uint32_t wdst = ws_u + buf * 8192;
        #pragma unroll
        for (int t = 0; t < 4; t++)
            cp16(wdst + (t * 128 + tid) * 16, wsrc + t * 128 + tid);
        // A tile: 64 rows x 256 B = 1024 x 16B chunks, 128 threads -> 8 each
        #pragma unroll
        for (int t = 0; t < 8; t++) {
            int i = t * 128 + tid;
            int row = i >> 4, seg = i & 15;
            int ic8 = row >> 3, ro = (row >> 1) & 3, p = row & 1;
            const float* asrc = Yb + ((size_t)(icb * 8 + ic8) * 192 + 8 * tr + 2 * ro + p) * 192
                                + tc * 64 + seg * 4;
            cp16(araw_u + buf * 16384 + row * 256 + seg * 16, asrc);
        }
        cp_commit();
    };

    issue(0, 0);
    for (int icb = 0; icb < 16; icb++) {
        int buf = icb & 1;
        if (icb < 15) {
            issue(icb + 1, buf ^ 1);
            asm volatile("cp.async.wait_group 1;");
        } else {
            asm volatile("cp.async.wait_group 0;");
        }
        __syncthreads();
        const float* A = Araw + buf * 4096;
        const float* W = Ws + buf * 2048;
        #pragma unroll 2
        for (int ko = 0; ko < 16; ko++) {
            int ic8 = ko >> 1, p = ko & 1;
            const float* r0 = A + (ic8 * 8 + 4 * rp + p) * 64 + 8 * cq;
            float4 A00 = *(const float4*)(r0);
            float4 A01 = *(const float4*)(r0 + 4);
            float4 A10 = *(const float4*)(r0 + 128);
            float4 A11 = *(const float4*)(r0 + 132);
            const float* wp = W + (ic8 * 4 + p * 2) * 64 + ocg * 8;
            float4 wq0a = *(const float4*)(wp);
            float4 wq0b = *(const float4*)(wp + 4);
            float4 wq1a = *(const float4*)(wp + 64);
            float4 wq1b = *(const float4*)(wp + 68);
            float w0[8] = {wq0a.x, wq0a.y, wq0a.z, wq0a.w, wq0b.x, wq0b.y, wq0b.z, wq0b.w};
            float w1[8] = {wq1a.x, wq1a.y, wq1a.z, wq1a.w, wq1b.x, wq1b.y, wq1b.z, wq1b.w};
            #pragma unroll
            for (int u = 0; u < 8; u++) {
                acc[0][u] += A00.x * w0[u] + A00.y * w1[u];
                acc[1][u] += A00.z * w0[u] + A00.w * w1[u];
                acc[2][u] += A01.x * w0[u] + A01.y * w1[u];
                acc[3][u] += A01.z * w0[u] + A01.w * w1[u];
                acc[4][u] += A10.x * w0[u] + A10.y * w1[u];
                acc[5][u] += A10.z * w0[u] + A10.w * w1[u];
                acc[6][u] += A11.x * w0[u] + A11.y * w1[u];
                acc[7][u] += A11.z * w0[u] + A11.w * w1[u];
            }
        }
        __syncthreads();
    }
    // maxpool 2x2 -> keys m0 (even), m0+1; store paired fp16 for PV B-fragments
    int m0 = (2 * tr + rp) * 48 + tc * 16 + 2 * cq;
    uint32_t pk[8];
    #pragma unroll
    for (int u = 0; u < 8; u++) {
        float bv = d_bg[ocg * 8 + u];
        float r0 = fmaxf(fmaxf(acc[0][u], acc[1][u]), fmaxf(acc[4][u], acc[5][u])) + bv;
        float r1 = fmaxf(fmaxf(acc[2][u], acc[3][u]), fmaxf(acc[6][u], acc[7][u])) + bv;
        __half2 h = __floats2half2_rn(r0, r1);
        pk[u] = *(uint32_t*)&h;
    }
    uint32_t* gdst = d_g2 + ((size_t)b * 1152 + (m0 >> 1)) * 64 + ocg * 8;
    *(uint4*)(gdst)     = make_uint4(pk[0], pk[1], pk[2], pk[3]);
    *(uint4*)(gdst + 4) = make_uint4(pk[4], pk[5], pk[6], pk[7]);
}

// ----------------- K4: flash attention, bf16-split QK + fp16 PV (Br=64, Bc=64, C=64) -----------------
// grid (144, 4), 128 threads (4 warps, one m16 q-row tile each)
// smem u32: KhiW[64x36]@0  KloW@2304  G2w[32x72]@4608  P2w[64x36]@6912  (36864 B total)
__global__ __launch_bounds__(128) void attn_tc() {
    extern __shared__ float sm[];
    uint32_t* KhiW = (uint32_t*)sm;
    uint32_t* KloW = KhiW + 2304;
    uint32_t* G2w  = KhiW + 4608;
    uint32_t* P2w  = KhiW + 6912;
    int b = blockIdx.y;
    int n0 = blockIdx.x * 64;
    int tid = threadIdx.x;
    int w = tid >> 5, lane = tid & 31;
    int g = lane >> 2, tig = lane & 3;
    int qa = n0 + w * 16 + g, qb = qa + 8;

    uint32_t sm_u32 = (uint32_t)__cvta_generic_to_shared(sm);
    int lr = lane & 7, sel = lane >> 3;
    // K LDSM per-lane offset: mats = {Khi b0, Khi b1, Klo b0, Klo b1}; row stride 144B
    uint32_t koff = (uint32_t)(lr * 144 + (sel & 1) * 16 + ((sel >> 1) ? 9216 : 0));

    // Q fragments: 4 k16-steps, hi & lo packed bf16x2
    uint32_t Qhi[4][4], Qlo[4][4];
    {
        const uint32_t* qh = d_thQhi + (size_t)b * 9216 * 32;
        const uint32_t* ql = d_thQlo + (size_t)b * 9216 * 32;
        #pragma unroll
        for (int ks = 0; ks < 4; ks++) {
            Qhi[ks][0] = qh[(size_t)qa * 32 + ks * 8 + tig];
            Qhi[ks][1] = qh[(size_t)qb * 32 + ks * 8 + tig];
            Qhi[ks][2] = qh[(size_t)qa * 32 + ks * 8 + tig + 4];
            Qhi[ks][3] = qh[(size_t)qb * 32 + ks * 8 + tig + 4];
            Qlo[ks][0] = ql[(size_t)qa * 32 + ks * 8 + tig];
            Qlo[ks][1] = ql[(size_t)qb * 32 + ks * 8 + tig];
            Qlo[ks][2] = ql[(size_t)qa * 32 + ks * 8 + tig + 4];
            Qlo[ks][3] = ql[(size_t)qb * 32 + ks * 8 + tig + 4];
        }
    }
    float mA = -1e30f, mB = -1e30f, lA = 0.f, lB = 0.f;
    float O[8][4];
    #pragma unroll
    for (int nt = 0; nt < 8; nt++)
        #pragma unroll
        for (int u = 0; u < 4; u++) O[nt][u] = 0.f;

    const uint32_t* phw = (const uint32_t*)d_phihi + (size_t)b * 2304 * 32;
    const uint32_t* plw = (const uint32_t*)d_philo + (size_t)b * 2304 * 32;
    const uint4* gsrc = (const uint4*)(d_g2 + (size_t)b * 1152 * 64);

    for (int it = 0; it < 36; it++) {
        int m0 = it * 64;
        __syncthreads();
        #pragma unroll
        for (int t = 0; t < 16; t++) {
            int i = t * 128 + tid;
            int key = i >> 5, wd = i & 31;
            KhiW[key * 36 + wd] = phw[(size_t)(m0 + key) * 32 + wd];
            KloW[key * 36 + wd] = plw[(size_t)(m0 + key) * 32 + wd];
        }
        #pragma unroll
        for (int t = 0; t < 4; t++) {   // G: 32 pair-rows x 16 uint4
            int i = t * 128 + tid;
            int prow = i >> 4, c4 = (i & 15) * 4;
            *(uint4*)(G2w + prow * 72 + c4) = gsrc[((size_t)(m0 >> 1) + prow) * 16 + (i & 15)];
        }
        __syncthreads();
        // S = theta @ phi^T : split-bf16 (hh + hl + lh), m16n8k16
        float S[8][4];
        #pragma unroll
        for (int nt = 0; nt < 8; nt++) {
            S[nt][0] = 0.f; S[nt][1] = 0.f; S[nt][2] = 0.f; S[nt][3] = 0.f;
        }
        #pragma unroll
        for (int ks = 0; ks < 4; ks++) {
            #pragma unroll
            for (int nt = 0; nt < 8; nt++) {
                uint32_t kf[4];
                ldsm4(kf, sm_u32 + (uint32_t)(nt * 1152 + ks * 32) + koff);
                mma_bf16(S[nt], Qhi[ks], kf[0], kf[1]);
                mma_bf16(S[nt], Qhi[ks], kf[2], kf[3]);
                mma_bf16(S[nt], Qlo[ks], kf[0], kf[1]);
            }
        }
        // online softmax (logits in log2 domain)
        float mxA = -1e30f, mxB = -1e30f;
        #pragma unroll
        for (int nt = 0; nt < 8; nt++) {
            mxA = fmaxf(mxA, fmaxf(S[nt][0], S[nt][1]));
            mxB = fmaxf(mxB, fmaxf(S[nt][2], S[nt][3]));
        }
        mxA = fmaxf(mxA, __shfl_xor_sync(0xffffffffu, mxA, 1));
        mxA = fmaxf(mxA, __shfl_xor_sync(0xffffffffu, mxA, 2));
        mxB = fmaxf(mxB, __shfl_xor_sync(0xffffffffu, mxB, 1));
        mxB = fmaxf(mxB, __shfl_xor_sync(0xffffffffu, mxB, 2));
        float mnA = fmaxf(mA, mxA), mnB = fmaxf(mB, mxB);
        float aA = ex2f(mA - mnA), aB = ex2f(mB - mnB);
        mA = mnA; mB = mnB;
        float sumA = 0.f, sumB = 0.f;
        #pragma unroll
        for (int nt = 0; nt < 8; nt++) {
            S[nt][0] = ex2f(S[nt][0] - mA);
            S[nt][1] = ex2f(S[nt][1] - mA);
            S[nt][2] = ex2f(S[nt][2] - mB);
            S[nt][3] = ex2f(S[nt][3] - mB);
            sumA += S[nt][0] + S[nt][1];
            sumB += S[nt][2] + S[nt][3];
        }
        sumA += __shfl_xor_sync(0xffffffffu, sumA, 1);
        sumA += __shfl_xor_sync(0xffffffffu, sumA, 2);
        sumB += __shfl_xor_sync(0xffffffffu, sumB, 1);
        sumB += __shfl_xor_sync(0xffffffffu, sumB, 2);
        lA = lA * aA + sumA;
        lB = lB * aB + sumB;
        #pragma unroll
        for (int nt = 0; nt < 8; nt++) {
            O[nt][0] *= aA; O[nt][1] *= aA; O[nt][2] *= aB; O[nt][3] *= aB;
        }
        // store P as packed half2 pairs (k even, k odd) to per-warp rows
        int q0 = w * 16 + g;
        #pragma unroll
        for (int nt = 0; nt < 8; nt++) {
            __half2 hA = __floats2half2_rn(S[nt][0], S[nt][1]);
            __half2 hB = __floats2half2_rn(S[nt][2], S[nt][3]);
            P2w[q0 * 36 + 4 * nt + tig]       = *(uint32_t*)&hA;
            P2w[(q0 + 8) * 36 + 4 * nt + tig] = *(uint32_t*)&hB;
        }
        __syncwarp();
        // O += P @ G   fp16 m16n8k16 (scalar frags, conflict-free)
        #pragma unroll
        for (int kt = 0; kt < 4; kt++) {
            uint32_t a[4];
            const uint32_t* PR = P2w + (w * 16 + g) * 36 + kt * 8 + tig;
            a[0] = PR[0];
            a[1] = PR[8 * 36];
            a[2] = PR[4];
            a[3] = PR[8 * 36 + 4];
            const uint32_t* GR = G2w + (kt * 8 + tig) * 72 + g;
            #pragma unroll
            for (int nt = 0; nt < 8; nt++) {
                uint32_t b0 = GR[nt * 8];
                uint32_t b1 = GR[4 * 72 + nt * 8];
                mma_fp16(O[nt], a, b0, b1);
            }
        }
    }
    // normalize + transpose through smem (reuse K region) + coalesced write to d_omap [b][c][n]
    __syncthreads();
    float* stage = sm;     // [64 ch][68 q] floats = 17408 B (fits in K region 18432 B)
    float ilA = 1.f / lA, ilB = 1.f / lB;
    int q0 = w * 16 + g;
    #pragma unroll
    for (int nt = 0; nt < 8; nt++) {
        int ch = nt * 8 + 2 * tig;
        stage[ch * 68 + q0]           = O[nt][0] * ilA;
        stage[(ch + 1) * 68 + q0]     = O[nt][1] * ilA;
        stage[ch * 68 + q0 + 8]       = O[nt][2] * ilB;
        stage[(ch + 1) * 68 + q0 + 8] = O[nt][3] * ilB;
    }
    __syncthreads();
    float* om = d_omap + (size_t)b * 64 * 9216 + n0;
    for (int i = tid; i < 1024; i += 128) {
        int ch = i >> 4, c4 = (i & 15) * 4;
        *(float4*)(om + (size_t)ch * 9216 + c4) = *(float4*)(stage + ch * 68 + c4);
    }
}

// ----------------- K5: fused (o_w o up) + bias + gamma*y, coalesced out -----------------
// grid (3, 48, 16): z = b*4 + ocb ; dynamic smem 49152B
__global__ __launch_bounds__(256) void out_k(const float* __restrict__ Y,
                                             const float* __restrict__ up_b,
                                             const float* __restrict__ gammap,
                                             float* __restrict__ out) {
    extern __shared__ float sm[];
    float* Os = sm;           // [c2][px] 64*64
    float* Ws = sm + 4096;    // [c2][row] 64*128 ; later reused as 32x4x64 staging
    int tc = blockIdx.x, tr = blockIdx.y;
    int b = blockIdx.z >> 2, ocb = blockIdx.z & 3;
    int tid = threadIdx.x;
    int og = tid & 15, pg = tid >> 4;
    for (int i = tid; i < 2048; i += 256) {
        int c2 = i >> 5, r4 = i & 31;
        ((float4*)Ws)[i] = *(const float4*)(d_W2 + c2 * 512 + ocb * 128 + r4 * 4);
    }
    for (int i = tid; i < 1024; i += 256) {
        int c2 = i >> 4, s4 = i & 15;
        int r = s4 >> 3, jc = (s4 & 7) * 4;
        ((float4*)Os)[i] = *(const float4*)(d_omap + ((size_t)b * 64 + c2) * 9216
                                            + (2 * tr + r) * 96 + tc * 32 + jc);
    }
    __syncthreads();
    float acc[4][8];
    #pragma unroll
    for (int i = 0; i < 4; i++)
        #pragma unroll
        for (int u = 0; u < 8; u++) acc[i][u] = 0.f;
    #pragma unroll 4
    for (int c2 = 0; c2 < 64; c2++) {
        const float* Ar = Os + c2 * 64;
        float2 a01 = *(const float2*)(Ar + 2 * pg);
        float2 a23 = *(const float2*)(Ar + 32 + 2 * pg);
        const float* Wr = Ws + c2 * 128 + og * 8;
        float4 w0 = *(const float4*)(Wr);
        float4 w1 = *(const float4*)(Wr + 4);
        float wv[8] = {w0.x, w0.y, w0.z, w0.w, w1.x, w1.y, w1.z, w1.w};
        #pragma unroll
        for (int u = 0; u < 8; u++) {
            acc[0][u] += a01.x * wv[u];
            acc[1][u] += a01.y * wv[u];
            acc[2][u] += a23.x * wv[u];
            acc[3][u] += a23.y * wv[u];
        }
    }
    __syncthreads();
    float* stg = Ws;   // 32 oc x 4 lrow x 64 col
    #pragma unroll
    for (int u = 0; u < 8; u++) {
        int row = og * 8 + u;
        int oc_l = row >> 2, p = (row >> 1) & 1, q = row & 1;
        #pragma unroll
        for (int px = 0; px < 4; px++) {
            int r = px >> 1;
            int jc = 2 * pg + (px & 1);
            stg[oc_l * 256 + (2 * r + p) * 64 + 2 * jc + q] = acc[px][u];
        }
    }
    __syncthreads();
    float gamma = *gammap;
    for (int i = tid; i < 2048; i += 256) {
        int col4 = i & 15, lrow = (i >> 4) & 3, oc_l = i >> 6;
        int oc = ocb * 32 + oc_l;
        size_t gaddr = (((size_t)b * 128 + oc) * 192 + (4 * tr + lrow)) * 192 + tc * 64 + col4 * 4;
        float4 s = ((float4*)stg)[oc_l * 64 + lrow * 16 + col4];
        float4 yv = *(const float4*)(Y + gaddr);
        float bb = up_b[oc];
        float4 o = make_float4(s.x + bb + gamma * yv.x, s.y + bb + gamma * yv.y,
                               s.z + bb + gamma * yv.z, s.w + bb + gamma * yv.w);
        *(float4*)(out + gaddr) = o;
    }
}

// ----------------- launch -----------------
extern "C" void kernel_launch(void* const* d_in, const int* in_sizes, int n_in,
                              void* d_out, int out_size) {
    (void)in_sizes; (void)n_in; (void)out_size;
    const float* input_x = (const float*)d_in[0];
    const float* input_y = (const float*)d_in[1];
    const float* down0_w = (const float*)d_in[2];
    const float* down0_b = (const float*)d_in[3];
    const float* down1_w = (const float*)d_in[4];
    const float* down1_b = (const float*)d_in[5];
    const float* theta_w = (const float*)d_in[6];
    const float* phi_w   = (const float*)d_in[7];
    const float* g_w     = (const float*)d_in[8];
    const float* o_w     = (const float*)d_in[9];
    const float* up_w    = (const float*)d_in[10];
    const float* up_b    = (const float*)d_in[11];
    const float* gamma   = (const float*)d_in[12];
    float* out = (float*)d_out;

    cudaFuncSetAttribute(conv_tp, cudaFuncAttributeMaxDynamicSharedMemorySize, 65536);
    cudaFuncSetAttribute(conv_g, cudaFuncAttributeMaxDynamicSharedMemorySize, 49152);
    cudaFuncSetAttribute(attn_tc, cudaFuncAttributeMaxDynamicSharedMemorySize, 36864);

    fuse_tp<<<64, 256>>>(theta_w, phi_w, down0_w, down0_b);
    fuse_g<<<32, 256>>>(g_w, down1_w, down1_b);
    fuse_w2<<<32, 256>>>(o_w, up_w);
    conv_tp<<<dim3(3, 24, 4), 256, 65536>>>(input_x);
    conv_g<<<dim3(3, 24, 4), 128, 49152>>>(input_y);
    attn_tc<<<dim3(144, 4), 128, 36864>>>();
    out_k<<<dim3(3, 48, 16), 256, 49152>>>(input_y, up_b, gamma, out);
}